// round 1
// baseline (speedup 1.0000x reference)
#include <cuda_runtime.h>
#include <cuda_fp16.h>

// Problem constants
#define NC     5
#define NB     128000
#define BATCH  8
#define NJ     15
#define HH     128
#define WW     240
#define HMPIX  (HH*WW)        // 30720 pixels per (b,cam,j) heatmap

// Main kernel tiling
#define THREADS 512
#define BPT     50            // bins per thread (register accumulators)
#define CHUNK   (THREADS*BPT) // 25600 bins per CTA
#define NCHUNK  (NB/CHUNK)    // 5 chunks -> grid 5 x 15 x 8 = 600 CTAs

// Precomputed per-(cam,bin) sampling records (shared across all b,j):
//  g_off: uint16 offset of the top-left *pair* in the padded smem heatmap
//         (off fits in 15 bits: <= 127*240+239 = 30719). Bottom row pair is
//         always off+240 (row 128 in smem is a zero pad row).
//  g_wts: 4 bilinear weights as 2x half2: (w00,w01),(w10,w11), with border
//         (zeros padding) handling folded into the weights.
__device__ unsigned short g_off[NC*NB];
__device__ uint2          g_wts[NC*NB];

__global__ void prep_kernel(const float* __restrict__ grid) {
    int idx = blockIdx.x * 256 + threadIdx.x;
    if (idx >= NC*NB) return;
    float2 g = reinterpret_cast<const float2*>(grid)[idx];

    // align_corners=True mapping
    float ix = (g.x + 1.0f) * 0.5f * (float)(WW - 1);
    float iy = (g.y + 1.0f) * 0.5f * (float)(HH - 1);
    float x0f = floorf(ix), y0f = floorf(iy);
    float fx = ix - x0f,    fy = iy - y0f;
    int   x0 = (int)x0f,    y0 = (int)y0f;

    // Column handling: pair at xc provides (hm[y][xc], hm[y][xc+1]); the pair
    // builder zero-pads the second element at xc==WW-1, so an invalid x1
    // corner naturally contributes 0 there.
    float wA, wB; int xc;
    if (x0 >= 0 && x0 < WW) { xc = x0; wA = 1.0f - fx; wB = fx;  }
    else if (x0 == -1)      { xc = 0;  wA = fx;        wB = 0.f; } // only x1=0 valid
    else                    { xc = 0;  wA = 0.f;       wB = 0.f; } // fully OOB in x

    // Row handling: smem row 128 is all zeros, so y0==HH-1 (y1 OOB) is safe.
    float wy0, wy1; int yc;
    if (y0 >= 0 && y0 < HH) { yc = y0; wy0 = 1.0f - fy; wy1 = fy;  }
    else if (y0 == -1)      { yc = 0;  wy0 = fy;        wy1 = 0.f; } // only y1=0 valid
    else                    { yc = 0;  wy0 = 0.f;       wy1 = 0.f; } // fully OOB in y

    g_off[idx] = (unsigned short)(yc * WW + xc);

    __half2 h01 = __floats2half2_rn(wy0 * wA, wy0 * wB);
    __half2 h23 = __floats2half2_rn(wy1 * wA, wy1 * wB);
    uint2 w;
    w.x = *reinterpret_cast<unsigned int*>(&h01);
    w.y = *reinterpret_cast<unsigned int*>(&h23);
    g_wts[idx] = w;
}

__global__ __launch_bounds__(THREADS, 1)
void sample_kernel(const float* __restrict__ heatmaps,
                   float* __restrict__ out) {
    // Padded pair-heatmap: (HH+1) rows x WW pairs of fp16. 123,840 bytes.
    extern __shared__ __half2 sp[];

    const int tid   = threadIdx.x;
    const int chunk = blockIdx.x;
    const int j     = blockIdx.y;
    const int b     = blockIdx.z;
    const int base  = chunk * CHUNK;

    // Zero the pad row (row HH) once — fills below never touch it.
    if (tid < WW) sp[HMPIX + tid] = __floats2half2_rn(0.f, 0.f);

    float acc[BPT];
#pragma unroll
    for (int k = 0; k < BPT; ++k) acc[k] = 0.f;

    for (int cam = 0; cam < NC; ++cam) {
        __syncthreads();  // previous gathers done (and pad-row visible, iter 0)

        // Build fp16 x-pair heatmap in smem from the fp32 global heatmap.
        const float* hm = heatmaps + (((size_t)b * NC + cam) * NJ + j) * (size_t)HMPIX;
        for (int i = tid; i < HMPIX; i += THREADS) {
            int x = i % WW;
            float v0 = __ldg(hm + i);
            float v1 = (x < WW - 1) ? __ldg(hm + i + 1) : 0.f;
            sp[i] = __floats2half2_rn(v0, v1);
        }
        __syncthreads();

        const unsigned short* __restrict__ op = g_off + cam * NB + base;
        const uint2*          __restrict__ wp = g_wts + cam * NB + base;

#pragma unroll
        for (int k = 0; k < BPT; ++k) {
            int i = k * THREADS + tid;
            unsigned int off = op[i];
            uint2 w = wp[i];
            __half2 w01 = *reinterpret_cast<const __half2*>(&w.x);
            __half2 w23 = *reinterpret_cast<const __half2*>(&w.y);
            __half2 p0  = sp[off];        // (hm[y0][x0], hm[y0][x1])
            __half2 p1  = sp[off + WW];   // (hm[y1][x0], hm[y1][x1])
            __half2 s   = __hfma2(p1, w23, __hmul2(p0, w01));
            float2 sf   = __half22float2(s);
            acc[k] += sf.x + sf.y;        // fp32 accumulation across corners/cams
        }
    }

    float* o = out + ((size_t)(b * NJ + j)) * NB + base;
#pragma unroll
    for (int k = 0; k < BPT; ++k) {
        float v = acc[k] * 0.2f;                       // mean over 5 cams
        o[k * THREADS + tid] = fminf(fmaxf(v, 0.f), 1.f);  // clip [0,1]
    }
}

extern "C" void kernel_launch(void* const* d_in, const int* in_sizes, int n_in,
                              void* d_out, int out_size) {
    const float* heatmaps = (const float*)d_in[0];
    const float* grid     = (const float*)d_in[1];
    // Robustness: identify inputs by element count if order differs.
    if (n_in >= 2 && in_sizes[0] == NC * NB * 2) {
        grid     = (const float*)d_in[0];
        heatmaps = (const float*)d_in[1];
    }

    const int smem_bytes = (HH + 1) * WW * (int)sizeof(__half2);  // 123,840 B
    cudaFuncSetAttribute(sample_kernel,
                         cudaFuncAttributeMaxDynamicSharedMemorySize, smem_bytes);

    prep_kernel<<<(NC * NB + 255) / 256, 256>>>(grid);

    dim3 g(NCHUNK, NJ, BATCH);
    sample_kernel<<<g, THREADS, smem_bytes>>>(heatmaps, (float*)d_out);
}

// round 2
// speedup vs baseline: 1.1915x; 1.1915x over previous
#include <cuda_runtime.h>
#include <cuda_fp16.h>

// Problem constants
#define NC     5
#define NB     128000
#define BATCH  8
#define NJ     15
#define HH     128
#define WW     240
#define HMPIX  (HH*WW)        // 30720 pixels per (b,cam,j) heatmap

// Main kernel tiling: 1024 threads (32 warps) to lift occupancy to ~50%
// (smem 123.8KB forces 1 CTA/SM; warps are the only latency-hiding lever).
#define THREADS 1024
#define BPT     25            // bins per thread (register accumulators)
#define CHUNK   (THREADS*BPT) // 25600 bins per CTA
#define NCHUNK  (NB/CHUNK)    // 5 chunks -> grid 5 x 15 x 8 = 600 CTAs

// Precomputed per-(cam,bin) sampling records (shared across all b,j):
//  g_off: uint16 offset of the top-left *pair* in the padded smem heatmap.
//  g_wts: 4 bilinear weights as 2x half2, border handling folded in.
__device__ unsigned short g_off[NC*NB];
__device__ uint2          g_wts[NC*NB];

__global__ void prep_kernel(const float* __restrict__ grid) {
    int idx = blockIdx.x * 256 + threadIdx.x;
    if (idx >= NC*NB) return;
    float2 g = reinterpret_cast<const float2*>(grid)[idx];

    // align_corners=True mapping
    float ix = (g.x + 1.0f) * 0.5f * (float)(WW - 1);
    float iy = (g.y + 1.0f) * 0.5f * (float)(HH - 1);
    float x0f = floorf(ix), y0f = floorf(iy);
    float fx = ix - x0f,    fy = iy - y0f;
    int   x0 = (int)x0f,    y0 = (int)y0f;

    // Column: pair at xc provides (hm[y][xc], hm[y][xc+1]); builder zero-pads
    // the second element at xc==WW-1, so invalid x1 contributes 0.
    float wA, wB; int xc;
    if (x0 >= 0 && x0 < WW) { xc = x0; wA = 1.0f - fx; wB = fx;  }
    else if (x0 == -1)      { xc = 0;  wA = fx;        wB = 0.f; }
    else                    { xc = 0;  wA = 0.f;       wB = 0.f; }

    // Row: smem row 128 is all zeros, so y0==HH-1 (y1 OOB) is safe.
    float wy0, wy1; int yc;
    if (y0 >= 0 && y0 < HH) { yc = y0; wy0 = 1.0f - fy; wy1 = fy;  }
    else if (y0 == -1)      { yc = 0;  wy0 = fy;        wy1 = 0.f; }
    else                    { yc = 0;  wy0 = 0.f;       wy1 = 0.f; }

    g_off[idx] = (unsigned short)(yc * WW + xc);

    __half2 h01 = __floats2half2_rn(wy0 * wA, wy0 * wB);
    __half2 h23 = __floats2half2_rn(wy1 * wA, wy1 * wB);
    uint2 w;
    w.x = *reinterpret_cast<unsigned int*>(&h01);
    w.y = *reinterpret_cast<unsigned int*>(&h23);
    g_wts[idx] = w;
}

__global__ __launch_bounds__(THREADS, 1)
void sample_kernel(const float* __restrict__ heatmaps,
                   float* __restrict__ out) {
    // Padded pair-heatmap: (HH+1) rows x WW pairs of fp16. 123,840 bytes.
    extern __shared__ __half2 sp[];

    const int tid   = threadIdx.x;
    const int chunk = blockIdx.x;
    const int j     = blockIdx.y;
    const int b     = blockIdx.z;
    const int base  = chunk * CHUNK;

    // Zero the pad row (row HH) once.
    if (tid < WW) sp[HMPIX + tid] = __floats2half2_rn(0.f, 0.f);

    // Fill-loop x coordinate, maintained incrementally (no per-pixel modulo).
    // step = THREADS % WW = 1024 % 240 = 64 (< WW, single conditional wrap).
    const int xstart = tid % WW;

    float acc[BPT];
#pragma unroll
    for (int k = 0; k < BPT; ++k) acc[k] = 0.f;

    for (int cam = 0; cam < NC; ++cam) {
        __syncthreads();  // previous gathers done (pad row visible, iter 0)

        // Build fp16 x-pair heatmap in smem from fp32 global heatmap.
        const float* hm = heatmaps + (((size_t)b * NC + cam) * NJ + j) * (size_t)HMPIX;
        int x = xstart;
#pragma unroll 6
        for (int i = tid; i < HMPIX; i += THREADS) {
            float v0 = __ldg(hm + i);
            float v1 = (x < WW - 1) ? __ldg(hm + i + 1) : 0.f;
            sp[i] = __floats2half2_rn(v0, v1);
            x += (THREADS % WW);
            if (x >= WW) x -= WW;
        }
        __syncthreads();

        const unsigned short* __restrict__ op = g_off + cam * NB + base;
        const uint2*          __restrict__ wp = g_wts + cam * NB + base;

#pragma unroll
        for (int k = 0; k < BPT; ++k) {
            int i = k * THREADS + tid;
            unsigned int off = __ldg(op + i);
            uint2 w = __ldg(wp + i);
            __half2 w01 = *reinterpret_cast<const __half2*>(&w.x);
            __half2 w23 = *reinterpret_cast<const __half2*>(&w.y);
            __half2 p0  = sp[off];        // (hm[y0][x0], hm[y0][x1])
            __half2 p1  = sp[off + WW];   // (hm[y1][x0], hm[y1][x1])
            __half2 s   = __hfma2(p1, w23, __hmul2(p0, w01));
            float2 sf   = __half22float2(s);
            acc[k] += sf.x + sf.y;        // fp32 accumulation across corners/cams
        }
    }

    float* o = out + ((size_t)(b * NJ + j)) * NB + base;
#pragma unroll
    for (int k = 0; k < BPT; ++k) {
        float v = acc[k] * 0.2f;                          // mean over 5 cams
        o[k * THREADS + tid] = fminf(fmaxf(v, 0.f), 1.f); // clip [0,1]
    }
}

extern "C" void kernel_launch(void* const* d_in, const int* in_sizes, int n_in,
                              void* d_out, int out_size) {
    const float* heatmaps = (const float*)d_in[0];
    const float* grid     = (const float*)d_in[1];
    if (n_in >= 2 && in_sizes[0] == NC * NB * 2) {
        grid     = (const float*)d_in[0];
        heatmaps = (const float*)d_in[1];
    }

    const int smem_bytes = (HH + 1) * WW * (int)sizeof(__half2);  // 123,840 B
    cudaFuncSetAttribute(sample_kernel,
                         cudaFuncAttributeMaxDynamicSharedMemorySize, smem_bytes);

    prep_kernel<<<(NC * NB + 255) / 256, 256>>>(grid);

    dim3 g(NCHUNK, NJ, BATCH);
    sample_kernel<<<g, THREADS, smem_bytes>>>(heatmaps, (float*)d_out);
}

// round 3
// speedup vs baseline: 2.0096x; 1.6867x over previous
#include <cuda_runtime.h>
#include <cuda_fp16.h>

// Problem constants
#define NC     5
#define NB     128000
#define BATCH  8
#define NJ     15
#define HH     128
#define WW     240
#define HMPIX  (HH*WW)        // 30720 pixels per (b,cam,j) heatmap

// Tiling: 1024 threads (32 warps). smem 123.8KB forces 1 CTA/SM; 32/64 warps.
#define THREADS 1024
#define BPT     25            // bins per thread (register accumulators)
#define CHUNK   (THREADS*BPT) // 25600 bins per CTA
#define NCHUNK  (NB/CHUNK)    // 5 chunks -> grid 5 x 15 x 8 = 600 CTAs

// Fused 8-byte per-(cam,bin) record (shared across all b,j):
//   .x = off (bits 0..15) | t_half_bits (bits 16..31)
//   .y = half2(vA, vB)
// Semantics: result = (vA,vB) . ( p0 + t*(p1-p0) )
// where p0 = pair at off (row y0), p1 = pair at off+WW (row y0+1; smem row 128
// is a zero pad row). All border (zeros-padding) cases are folded into
// (vA, vB, t) by the prep kernel.
__device__ uint2 g_rec[NC*NB];

__global__ void prep_kernel(const float* __restrict__ grid) {
    int idx = blockIdx.x * 256 + threadIdx.x;
    if (idx >= NC*NB) return;
    float2 g = reinterpret_cast<const float2*>(grid)[idx];

    // align_corners=True mapping
    float ix = (g.x + 1.0f) * 0.5f * (float)(WW - 1);
    float iy = (g.y + 1.0f) * 0.5f * (float)(HH - 1);
    float x0f = floorf(ix), y0f = floorf(iy);
    float fx = ix - x0f,    fy = iy - y0f;
    int   x0 = (int)x0f,    y0 = (int)y0f;

    // x handling: pair at xc provides (hm[y][xc], hm[y][xc+1]); the fill
    // zero-pads the second element at xc==WW-1, so invalid x1 contributes 0.
    float wA, wB; int xc;
    if (x0 >= 0 && x0 < WW) { xc = x0; wA = 1.0f - fx; wB = fx;  }
    else if (x0 == -1)      { xc = 0;  wA = fx;        wB = 0.f; }
    else                    { xc = 0;  wA = 0.f;       wB = 0.f; }

    // y handling folded into (t, s):
    //   interior (incl. y0==HH-1, pad row is zero): t = fy, s = 1
    //   y0 == -1 (only y1=0 valid): t = 0 (use row 0 only), s = fy
    //   fully OOB: s = 0
    float t, s; int yc;
    if (y0 >= 0 && y0 < HH) { yc = y0; t = fy;  s = 1.f; }
    else if (y0 == -1)      { yc = 0;  t = 0.f; s = fy;  }
    else                    { yc = 0;  t = 0.f; s = 0.f; }

    unsigned int off = (unsigned int)(yc * WW + xc);   // <= 30719, fits 15 bits
    __half th = __float2half_rn(t);
    __half2 v = __floats2half2_rn(wA * s, wB * s);

    uint2 r;
    r.x = off | ((unsigned int)__half_as_ushort(th) << 16);
    r.y = *reinterpret_cast<unsigned int*>(&v);
    g_rec[idx] = r;
}

__global__ __launch_bounds__(THREADS, 1)
void sample_kernel(const float* __restrict__ heatmaps,
                   float* __restrict__ out) {
    // Padded pair-heatmap: (HH+1) rows x WW pairs of fp16. 123,840 bytes.
    extern __shared__ __half2 sp[];

    const int tid   = threadIdx.x;
    const int chunk = blockIdx.x;
    const int j     = blockIdx.y;
    const int b     = blockIdx.z;
    const int base  = chunk * CHUNK;

    // Zero the pad row (row HH) once.
    if (tid < WW) sp[HMPIX + tid] = __floats2half2_rn(0.f, 0.f);

    // Vectorized fill coordinates: each thread handles 4 consecutive pixels
    // per iteration. Row width 240 is divisible by 4, so a float4 never
    // crosses a row. x (per-thread, of the float4's first pixel) is stepped
    // incrementally: delta = (THREADS*4) % WW = 4096 % 240 = 16.
    const int xstart = (tid * 4) % WW;

    float acc[BPT];
#pragma unroll
    for (int k = 0; k < BPT; ++k) acc[k] = 0.f;

    for (int cam = 0; cam < NC; ++cam) {
        __syncthreads();  // previous gathers done (pad row visible, iter 0)

        // Build fp16 x-pair heatmap in smem (vectorized: LDG.128 + STS.128).
        const float*  hm  = heatmaps + (((size_t)b * NC + cam) * NJ + j) * (size_t)HMPIX;
        const float4* hm4 = reinterpret_cast<const float4*>(hm);
        int x = xstart;
#pragma unroll
        for (int q = tid; q < HMPIX / 4; q += THREADS) {
            float4 v = __ldg(hm4 + q);
            // Neighbor pixel v[4q+4]: next lane's v.x; lane 31 loads it.
            float vn = __shfl_down_sync(0xffffffffu, v.x, 1);
            if ((tid & 31) == 31 && x != WW - 4)
                vn = __ldg(reinterpret_cast<const float*>(hm4 + q + 1));
            if (x == WW - 4) vn = 0.f;   // pair (239, OOB) -> zero pad

            __half2 h0 = __floats2half2_rn(v.x, v.y);
            __half2 h1 = __floats2half2_rn(v.y, v.z);
            __half2 h2 = __floats2half2_rn(v.z, v.w);
            __half2 h3 = __floats2half2_rn(v.w, vn);
            uint4 pk;
            pk.x = *reinterpret_cast<unsigned int*>(&h0);
            pk.y = *reinterpret_cast<unsigned int*>(&h1);
            pk.z = *reinterpret_cast<unsigned int*>(&h2);
            pk.w = *reinterpret_cast<unsigned int*>(&h3);
            *reinterpret_cast<uint4*>(sp + q * 4) = pk;

            x += 16;                      // (THREADS*4) % WW
            if (x >= WW) x -= WW;
        }
        __syncthreads();

        const uint2* __restrict__ rp = g_rec + cam * NB + base;

#pragma unroll
        for (int k = 0; k < BPT; ++k) {
            int i = k * THREADS + tid;
            uint2 r = __ldg(rp + i);
            unsigned int off = r.x & 0xFFFFu;
            __half2 t2  = __half2half2(__ushort_as_half((unsigned short)(r.x >> 16)));
            __half2 v01 = *reinterpret_cast<const __half2*>(&r.y);
            __half2 p0  = sp[off];        // (hm[y0][x0], hm[y0][x1])
            __half2 p1  = sp[off + WW];   // (hm[y1][x0], hm[y1][x1])
            __half2 pl  = __hfma2(__hsub2(p1, p0), t2, p0);   // row lerp
            __half2 pr  = __hmul2(pl, v01);                    // x weights
            float2 f    = __half22float2(pr);
            acc[k] += f.x + f.y;          // fp32 accumulation across cams
        }
    }

    float* o = out + ((size_t)(b * NJ + j)) * NB + base;
#pragma unroll
    for (int k = 0; k < BPT; ++k) {
        float v = acc[k] * 0.2f;                          // mean over 5 cams
        o[k * THREADS + tid] = fminf(fmaxf(v, 0.f), 1.f); // clip [0,1]
    }
}

extern "C" void kernel_launch(void* const* d_in, const int* in_sizes, int n_in,
                              void* d_out, int out_size) {
    const float* heatmaps = (const float*)d_in[0];
    const float* grid     = (const float*)d_in[1];
    if (n_in >= 2 && in_sizes[0] == NC * NB * 2) {
        grid     = (const float*)d_in[0];
        heatmaps = (const float*)d_in[1];
    }

    const int smem_bytes = (HH + 1) * WW * (int)sizeof(__half2);  // 123,840 B
    cudaFuncSetAttribute(sample_kernel,
                         cudaFuncAttributeMaxDynamicSharedMemorySize, smem_bytes);

    prep_kernel<<<(NC * NB + 255) / 256, 256>>>(grid);

    dim3 g(NCHUNK, NJ, BATCH);
    sample_kernel<<<g, THREADS, smem_bytes>>>(heatmaps, (float*)d_out);
}